// round 7
// baseline (speedup 1.0000x reference)
#include <cuda_runtime.h>
#include <cuda.h>
#include <cstdint>

// ============================================================
// MixedLinearV2 = GEMM out[8192,6144] = x[8192,1024] @ (W*M)^T + b*rowmask
//   M == 0 for o >= 3072 -> GEMM over o in [0,3072), zero-fill mirror inline.
// R4: cluster-4 TMA-multicast of B (4x L2 traffic cut on W tiles),
//     cp.async A, tcgen05 tf32, 4-stage pipeline, warp-specialized.
// ============================================================

#if defined(__CUDA_ARCH_SPECIFIC__) || defined(__CUDA_ARCH_FAMILY_SPECIFIC__) || \
    defined(__CUDA_ARCH_FEAT_SM103_ALL) || defined(__CUDA_ARCH_FEAT_SM100_ALL)
#define USE_TCGEN05 1
#else
#define USE_TCGEN05 0
#endif

#define BM 128
#define BN 256
#define BK 32
#define NKIT 32           // 1024 / 32
#define STAGES 4
#define THREADS 256
#define NPRODA 192        // warps 2..7 produce A
#define CLUSTER 4

// ---- scratch (static device globals: allowed, no allocation) ----
__device__ float g_xr[8192 * 1024];   // 32 MB, tf32-rounded x
__device__ float g_wr[3072 * 1024];   // 12 MB, tf32-rounded W * mask

// ---- smem layout (bytes); tiles 1024-aligned for SW128 descriptors ----
#define SM_TMEM      0
#define SM_FULL_A(s) (16 + (s) * 8)
#define SM_FULL_B(s) (48 + (s) * 8)
#define SM_EMPTY_A(s) (80 + (s) * 8)
#define SM_EMPTY_B(s) (112 + (s) * 8)
#define SM_FINAL     144
#define SM_A(s)      (1024 + (s) * 16384)          // 128x32 f32 = 16 KB
#define SM_B(s)      (66560 + (s) * 32768)         // 256x32 f32 = 32 KB
#define SM_TOTAL     197632

// idesc kind::tf32: dtype F32(bit4), atype TF32=2(7-9), btype TF32=2(10-12),
// N/8 @17, M/16 @24. K-major both.
static constexpr uint32_t IDESC_TF32 =
    (1u << 4) | (2u << 7) | (2u << 10) | ((BN / 8) << 17) | ((BM / 16) << 24);

// SW128 K-major: layout=2, version=1, SBO=64, LBO=1
static constexpr uint64_t DESC_BASE_SW128 =
    (uint64_t(2) << 61) | (uint64_t(1) << 46) | (uint64_t(64) << 32) | (uint64_t(1) << 16);
#define MK_DESC(addr) (DESC_BASE_SW128 | ((uint64_t)((addr) >> 4) & 0x3FFF))

// ---------------- PTX helpers ----------------
static __device__ __forceinline__ uint32_t smem_u32(const void* p) {
    uint32_t a;
    asm("{ .reg .u64 t; cvta.to.shared.u64 t, %1; cvt.u32.u64 %0, t; }" : "=r"(a) : "l"(p));
    return a;
}
static __device__ __forceinline__ uint32_t elect_one() {
    uint32_t p;
    asm volatile("{ .reg .pred p; elect.sync _|p, 0xFFFFFFFF; selp.b32 %0, 1, 0, p; }" : "=r"(p));
    return p;
}
static __device__ __forceinline__ float cvt_tf32(float x) {
    uint32_t r;
    asm("cvt.rna.tf32.f32 %0, %1;" : "=r"(r) : "f"(x));
    return __uint_as_float(r);
}
static __device__ __forceinline__ uint32_t cluster_rank() {
    uint32_t r;
    asm("mov.u32 %0, %%cluster_ctarank;" : "=r"(r));
    return r;
}

#define MBARRIER_INIT(mbar, cnt) \
    asm volatile("mbarrier.init.shared.b64 [%0], %1;" :: "r"((uint32_t)(mbar)), "r"((uint32_t)(cnt)) : "memory")
#define MBARRIER_EXPECT_TX(mbar, tx) \
    asm volatile("mbarrier.arrive.expect_tx.shared.b64 _, [%0], %1;" :: "r"((uint32_t)(mbar)), "r"((uint32_t)(tx)) : "memory")

#define MBARRIER_WAIT_PARITY(mbar_smem_addr, phase_parity) do { \
    uint32_t _mbar = (uint32_t)(mbar_smem_addr); \
    uint32_t _parity = (uint32_t)(phase_parity); \
    uint32_t _done; \
    asm volatile( \
        "{\n\t" \
        ".reg .pred p;\n\t" \
        "mbarrier.try_wait.parity.acquire.cta.shared::cta.b64 p, [%1], %2;\n\t" \
        "selp.b32 %0, 1, 0, p;\n\t" \
        "}" \
        : "=r"(_done) : "r"(_mbar), "r"(_parity) : "memory"); \
    if (!_done) { \
        asm volatile( \
            "{\n\t" \
            ".reg .pred P1;\n\t" \
            "WAIT_LOOP_%=:\n\t" \
            "mbarrier.try_wait.parity.acquire.cta.shared::cta.b64 P1, [%0], %1, 0x989680;\n\t" \
            "@P1 bra.uni WAIT_DONE_%=;\n\t" \
            "bra.uni WAIT_LOOP_%=;\n\t" \
            "WAIT_DONE_%=:\n\t" \
            "}" \
            :: "r"(_mbar), "r"(_parity) : "memory"); \
    } \
} while (0)

#define CP_ASYNC_CG(dst, src) \
    asm volatile("cp.async.cg.shared.global [%0], [%1], 16;" :: "r"((uint32_t)(dst)), "l"(src) : "memory")
#define CP_ASYNC_ARRIVE(mbar) \
    asm volatile("cp.async.mbarrier.arrive.noinc.shared::cta.b64 [%0];" :: "r"((uint32_t)(mbar)) : "memory")

#define TMA_B_MCAST(dst, map, cx, cy, mbar, mask) \
    asm volatile( \
        "cp.async.bulk.tensor.2d.shared::cluster.global.tile.mbarrier::complete_tx::bytes.multicast::cluster " \
        "[%0], [%1, {%2, %3}], [%4], %5;" \
        :: "r"((uint32_t)(dst)), "l"(map), "r"((int)(cx)), "r"((int)(cy)), \
           "r"((uint32_t)(mbar)), "h"((uint16_t)(mask)) : "memory")

#define TCGEN05_ALLOC(smem_result_addr, nCols) \
    asm volatile("tcgen05.alloc.cta_group::1.sync.aligned.shared::cta.b32 [%0], %1;" \
        :: "r"((uint32_t)(smem_result_addr)), "r"((uint32_t)(nCols)) : "memory")
#define TCGEN05_DEALLOC(tmem_addr, nCols) \
    asm volatile("tcgen05.dealloc.cta_group::1.sync.aligned.b32 %0, %1;" \
        :: "r"(tmem_addr), "r"((uint32_t)(nCols)))
#define TCGEN05_RELINQUISH() \
    asm volatile("tcgen05.relinquish_alloc_permit.cta_group::1.sync.aligned;")
#define TCGEN05_COMMIT(mbar_smem_addr) \
    asm volatile("tcgen05.commit.cta_group::1.mbarrier::arrive::one.shared::cluster.b64 [%0];" \
        :: "r"((uint32_t)(mbar_smem_addr)) : "memory")
#define TCGEN05_COMMIT_MC(mbar_smem_addr, mask) \
    asm volatile("tcgen05.commit.cta_group::1.mbarrier::arrive::one.shared::cluster.multicast::cluster.b64 [%0], %1;" \
        :: "r"((uint32_t)(mbar_smem_addr)), "h"((uint16_t)(mask)) : "memory")
#define TCGEN05_WAIT_LD() \
    asm volatile("tcgen05.wait::ld.sync.aligned;" ::: "memory")
#define TCGEN05_FENCE_BEFORE() \
    asm volatile("tcgen05.fence::before_thread_sync;" ::: "memory")
#define TCGEN05_FENCE_AFTER() \
    asm volatile("tcgen05.fence::after_thread_sync;" ::: "memory")
#define FENCE_PROXY_ASYNC() \
    asm volatile("fence.proxy.async.shared::cta;" ::: "memory")
#define CLUSTER_SYNC() do { \
    asm volatile("barrier.cluster.arrive.aligned;" ::: "memory"); \
    asm volatile("barrier.cluster.wait.aligned;" ::: "memory"); \
} while (0)

#define TCGEN05_LD_32X32B_X32(r, tmem_addr) \
    asm volatile( \
        "tcgen05.ld.sync.aligned.32x32b.x32.b32 " \
        "{%0, %1, %2, %3, %4, %5, %6, %7, " \
        " %8, %9, %10, %11, %12, %13, %14, %15, " \
        " %16, %17, %18, %19, %20, %21, %22, %23, " \
        " %24, %25, %26, %27, %28, %29, %30, %31}, [%32];" \
        : "=r"((r)[0]),  "=r"((r)[1]),  "=r"((r)[2]),  "=r"((r)[3]), \
          "=r"((r)[4]),  "=r"((r)[5]),  "=r"((r)[6]),  "=r"((r)[7]), \
          "=r"((r)[8]),  "=r"((r)[9]),  "=r"((r)[10]), "=r"((r)[11]), \
          "=r"((r)[12]), "=r"((r)[13]), "=r"((r)[14]), "=r"((r)[15]), \
          "=r"((r)[16]), "=r"((r)[17]), "=r"((r)[18]), "=r"((r)[19]), \
          "=r"((r)[20]), "=r"((r)[21]), "=r"((r)[22]), "=r"((r)[23]), \
          "=r"((r)[24]), "=r"((r)[25]), "=r"((r)[26]), "=r"((r)[27]), \
          "=r"((r)[28]), "=r"((r)[29]), "=r"((r)[30]), "=r"((r)[31]) \
        : "r"(tmem_addr))

static __device__ __forceinline__ void mma_tf32_cg1(
    uint32_t d_tmem, uint64_t a_desc, uint64_t b_desc, uint32_t idesc, uint32_t en) {
    asm volatile(
        "{\n\t"
        ".reg .pred p;\n\t"
        "setp.ne.u32 p, %4, 0;\n\t"
        "tcgen05.mma.cta_group::1.kind::tf32 [%0], %1, %2, %3, {%5, %5, %5, %5}, p;\n\t"
        "}"
        :: "r"(d_tmem), "l"(a_desc), "l"(b_desc), "r"(idesc), "r"(en), "r"(0u)
        : "memory");
}

static __device__ __forceinline__ uint32_t sw128(uint32_t off) {
    return off ^ ((off >> 3) & 0x70);
}

// ---------------- prepass kernels ----------------
__global__ void prep_x_kernel(const float* __restrict__ x) {
    const size_t i = ((size_t)blockIdx.x * blockDim.x + threadIdx.x) * 4;
    float4 v = *reinterpret_cast<const float4*>(x + i);
    v.x = cvt_tf32(v.x); v.y = cvt_tf32(v.y); v.z = cvt_tf32(v.z); v.w = cvt_tf32(v.w);
    *reinterpret_cast<float4*>(g_xr + i) = v;
}

__global__ void prep_w_kernel(const float* __restrict__ W, const float* __restrict__ wv) {
    const float s45  = wv[4] + wv[5];
    const float s23  = wv[2] + wv[3] + s45;
    const float sall = wv[0] + wv[1] + s23;
    const size_t i = ((size_t)blockIdx.x * blockDim.x + threadIdx.x) * 4;  // < 3072*1024
    const int o = (int)(i >> 10);
    const int k = (int)(i & 1023);
    const int ob = (o >= 1536) + (o >= 2304);
    float m;
    if (k >= 768)       m = s45;
    else if (k >= 512)  m = (ob <= 1) ? s23 : s45;
    else                m = (ob == 0) ? sall : (ob == 1 ? s23 : s45);
    float4 v = *reinterpret_cast<const float4*>(W + i);
    v.x = cvt_tf32(v.x * m); v.y = cvt_tf32(v.y * m);
    v.z = cvt_tf32(v.z * m); v.w = cvt_tf32(v.w * m);
    *reinterpret_cast<float4*>(g_wr + i) = v;
}

// ---------------- GEMM kernel ----------------
__global__ void __launch_bounds__(THREADS, 1) __cluster_dims__(CLUSTER, 1, 1)
gemm_tf32_kernel(const float* __restrict__ x, const float* __restrict__ wv,
                 const float* __restrict__ W, const float* __restrict__ bias,
                 float* __restrict__ out,
                 const __grid_constant__ CUtensorMap tmap) {
    const int t = threadIdx.x;
    const int g = blockIdx.x;
#if USE_TCGEN05
    const uint32_t rank = cluster_rank();
    const int c = g >> 2;                       // cluster index, [0,192)
    const int n0 = (c % 12) * BN;
    const int m0 = ((c / 12) * 4 + (int)rank) * BM;
#else
    const int n0 = (g % 12) * BN;
    const int m0 = (g / 12) * BM;
#endif

    const float s45  = wv[4] + wv[5];
    const float s23  = wv[2] + wv[3] + s45;
    const float sall = wv[0] + wv[1] + s23;
    const int oband = (n0 >= 1536) + (n0 >= 2304);
    const float bscale = (oband == 0) ? sall : (oband == 1 ? s23 : s45);

#if USE_TCGEN05
    extern __shared__ char smem[];
    const uint32_t sb = smem_u32(smem);
    const int wid = t >> 5;
    const int lid = t & 31;

    if (wid == 0) {
        if (elect_one()) {
#pragma unroll
            for (int s = 0; s < STAGES; ++s) {
                MBARRIER_INIT(sb + SM_FULL_A(s), NPRODA);
                MBARRIER_INIT(sb + SM_FULL_B(s), 1);       // expect_tx arrival
                MBARRIER_INIT(sb + SM_EMPTY_A(s), 1);      // local commit
                MBARRIER_INIT(sb + SM_EMPTY_B(s), CLUSTER); // 4 multicast commits
            }
            MBARRIER_INIT(sb + SM_FINAL, 1);
        }
        TCGEN05_ALLOC(sb + SM_TMEM, 256);
    }

    // ---- zero-fill mirror tile (m0, n0+3072), 128 x 256 ----
    {
        float* zt = out + (size_t)m0 * 6144 + n0 + 3072;
        const float4 z = make_float4(0.f, 0.f, 0.f, 0.f);
#pragma unroll
        for (int j = 0; j < 32; ++j) {
            const int idx = t + j * THREADS;     // < 8192
            const int row = idx >> 6, c4 = idx & 63;
            *reinterpret_cast<float4*>(zt + (size_t)row * 6144 + c4 * 4) = z;
        }
    }
    __syncthreads();
    uint32_t tmem;
    asm volatile("ld.shared.b32 %0, [%1];" : "=r"(tmem) : "r"(sb + SM_TMEM));
    CLUSTER_SYNC();   // all CTAs' barriers initialized before any multicast TMA

    if (wid == 0) {
        // ---- MMA issuer ----
        if (elect_one()) {
            int faph[STAGES] = {0, 0, 0, 0};
            int fbph[STAGES] = {0, 0, 0, 0};
#pragma unroll 1
            for (int it = 0; it < NKIT; ++it) {
                const int s = it & (STAGES - 1);
                MBARRIER_WAIT_PARITY(sb + SM_FULL_A(s), faph[s]); faph[s] ^= 1;
                MBARRIER_WAIT_PARITY(sb + SM_FULL_B(s), fbph[s]); fbph[s] ^= 1;
                FENCE_PROXY_ASYNC();
                const uint64_t ad = MK_DESC(sb + SM_A(s));
                const uint64_t bd = MK_DESC(sb + SM_B(s));
#pragma unroll
                for (int ks = 0; ks < 4; ++ks)
                    mma_tf32_cg1(tmem, ad + ks * 2, bd + ks * 2, IDESC_TF32,
                                 (uint32_t)(it > 0 || ks > 0));
                TCGEN05_COMMIT(sb + SM_EMPTY_A(s));
                TCGEN05_COMMIT_MC(sb + SM_EMPTY_B(s), 0xF);
            }
            TCGEN05_COMMIT(sb + SM_FINAL);
        }
    } else if (wid == 1) {
        // ---- B producer: multicast TMA, cooperative 64-row slices ----
        if (elect_one()) {
            const int ybase = n0 + (int)rank * 64;
            const uint32_t doff = rank * 8192;
#pragma unroll
            for (int it = 0; it < STAGES; ++it) {
                MBARRIER_EXPECT_TX(sb + SM_FULL_B(it), 32768);
                TMA_B_MCAST(sb + SM_B(it) + doff, &tmap, it * BK, ybase,
                            sb + SM_FULL_B(it), 0xF);
            }
            int beph[STAGES] = {0, 0, 0, 0};
#pragma unroll 1
            for (int it = STAGES; it < NKIT; ++it) {
                const int s = it & (STAGES - 1);
                MBARRIER_WAIT_PARITY(sb + SM_EMPTY_B(s), beph[s]); beph[s] ^= 1;
                MBARRIER_EXPECT_TX(sb + SM_FULL_B(s), 32768);
                TMA_B_MCAST(sb + SM_B(s) + doff, &tmap, it * BK, ybase,
                            sb + SM_FULL_B(s), 0xF);
            }
        }
    } else {
        // ---- A producers: warps 2..7, cp.async ----
        const int p = t - 64;  // 0..191
        int eph[STAGES] = {0, 0, 0, 0};
        const float* abase = g_xr + (size_t)m0 * 1024;
#pragma unroll 1
        for (int nt = 0; nt < NKIT; ++nt) {
            const int s = nt & (STAGES - 1);
            if (nt >= STAGES) {
                MBARRIER_WAIT_PARITY(sb + SM_EMPTY_A(s), eph[s]); eph[s] ^= 1;
            }
            const float* ak = abase + nt * BK;
            const uint32_t sa = sb + SM_A(s);
#pragma unroll
            for (int j = 0; j < 6; ++j) {
                const int i = p + j * NPRODA;
                if (i < 1024) {
                    const int r = i >> 3, q = i & 7;
                    CP_ASYNC_CG(sa + sw128((uint32_t)(r * 128 + q * 16)),
                                ak + (size_t)r * 1024 + q * 4);
                }
            }
            CP_ASYNC_ARRIVE(sb + SM_FULL_A(s));
        }
    }

    // ---- all threads: wait for all MMAs, epilogue ----
    MBARRIER_WAIT_PARITY(sb + SM_FINAL, 0);
    TCGEN05_FENCE_AFTER();

    const int wg  = wid >> 2;
    const int row = (wid & 3) * 32 + lid;
    float* orow = out + (size_t)(m0 + row) * 6144 + n0;
#pragma unroll
    for (int r4 = 0; r4 < 4; ++r4) {
        const int cb = wg * 128 + r4 * 32;
        uint32_t dr[32];
        TCGEN05_LD_32X32B_X32(dr, tmem + cb);
        TCGEN05_WAIT_LD();
#pragma unroll
        for (int cc = 0; cc < 32; cc += 4) {
            const int col = n0 + cb + cc;
            float4 v;
            v.x = __uint_as_float(dr[cc + 0]) + bias[col + 0] * bscale;
            v.y = __uint_as_float(dr[cc + 1]) + bias[col + 1] * bscale;
            v.z = __uint_as_float(dr[cc + 2]) + bias[col + 2] * bscale;
            v.w = __uint_as_float(dr[cc + 3]) + bias[col + 3] * bscale;
            *reinterpret_cast<float4*>(orow + cb + cc) = v;
        }
    }
    TCGEN05_FENCE_BEFORE();
    __syncthreads();
    if (wid == 0) {
        TCGEN05_RELINQUISH();
        TCGEN05_DEALLOC(tmem, 256);
    }
    CLUSTER_SYNC();   // no CTA exits while peer multicast may target its smem
#else
    // SIMT fallback for the family-generic PTX pass (never executed on GB300).
    float mv0, mv1, mv2;
    if (oband == 0)      { mv0 = sall; mv1 = s23; mv2 = s45; }
    else if (oband == 1) { mv0 = s23;  mv1 = s23; mv2 = s45; }
    else                 { mv0 = s45;  mv1 = s45; mv2 = s45; }
    for (int e = t; e < BM * BN; e += THREADS) {
        const int r = e / BN, cc = e % BN;
        const float* xr = x + (size_t)(m0 + r) * 1024;
        const float* wr = W + (size_t)(n0 + cc) * 1024;
        float acc = 0.f;
        for (int k = 0; k < 1024; ++k) {
            const float m = (k < 512) ? mv0 : (k < 768 ? mv1 : mv2);
            acc += xr[k] * wr[k] * m;
        }
        out[(size_t)(m0 + r) * 6144 + n0 + cc] = acc + bias[n0 + cc] * bscale;
        out[(size_t)(m0 + r) * 6144 + n0 + cc + 3072] = 0.f;
    }
#endif
}

// ---------------- launcher ----------------
typedef CUresult (*PFN_tmap_encode)(
    CUtensorMap*, CUtensorMapDataType, cuuint32_t, void*,
    const cuuint64_t*, const cuuint64_t*, const cuuint32_t*, const cuuint32_t*,
    CUtensorMapInterleave, CUtensorMapSwizzle, CUtensorMapL2promotion,
    CUtensorMapFloatOOBfill);

extern "C" void kernel_launch(void* const* d_in, const int* in_sizes, int n_in,
                              void* d_out, int out_size) {
    const float *x = nullptr, *wv = nullptr, *W = nullptr, *b = nullptr;
    for (int i = 0; i < n_in; ++i) {
        switch (in_sizes[i]) {
            case 8388608: x  = (const float*)d_in[i]; break;
            case 6:       wv = (const float*)d_in[i]; break;
            case 6291456: W  = (const float*)d_in[i]; break;
            case 6144:    b  = (const float*)d_in[i]; break;
        }
    }
    if (!x)  x  = (const float*)d_in[0];
    if (!wv) wv = (const float*)d_in[1];
    if (!W)  W  = (const float*)d_in[2];
    if (!b)  b  = (const float*)d_in[3];
    float* out = (float*)d_out;

    // ---- build tensormap for g_wr [3072 x 1024] f32, box [32 x 64], SW128 ----
    CUtensorMap tmap;
    {
        void* wr_ptr = nullptr;
        cudaGetSymbolAddress(&wr_ptr, g_wr);
        PFN_tmap_encode enc = nullptr;
        cudaDriverEntryPointQueryResult st;
        cudaGetDriverEntryPointByVersion("cuTensorMapEncodeTiled", (void**)&enc,
                                         12000, cudaEnableDefault, &st);
        cuuint64_t dims[2]    = {1024, 3072};
        cuuint64_t strides[1] = {1024 * sizeof(float)};
        cuuint32_t box[2]     = {BK, 64};
        cuuint32_t estr[2]    = {1, 1};
        enc(&tmap, CU_TENSOR_MAP_DATA_TYPE_FLOAT32, 2, wr_ptr,
            dims, strides, box, estr,
            CU_TENSOR_MAP_INTERLEAVE_NONE, CU_TENSOR_MAP_SWIZZLE_128B,
            CU_TENSOR_MAP_L2_PROMOTION_L2_128B, CU_TENSOR_MAP_FLOAT_OOB_FILL_NONE);
    }

    cudaFuncSetAttribute(gemm_tf32_kernel,
                         cudaFuncAttributeMaxDynamicSharedMemorySize, SM_TOTAL);

    prep_x_kernel<<<8192, 256>>>(x);
    prep_w_kernel<<<3072, 256>>>(W, wv);
    gemm_tf32_kernel<<<768, THREADS, SM_TOTAL>>>(x, wv, W, b, out, tmap);
}

// round 8
// speedup vs baseline: 1.0853x; 1.0853x over previous
#include <cuda_runtime.h>
#include <cuda.h>
#include <cstdint>

// ============================================================
// MixedLinearV2 = GEMM out[8192,6144] = x[8192,1024] @ (W*M)^T + b*rowmask
//   M == 0 for o >= 3072 -> GEMM over o in [0,3072), zero-fill mirror inline.
// R5: cg2 (2-CTA) tcgen05 tf32 MMA, tile 256(M)x256(N)x32(K), cluster (2,1,1).
//     A split 128 M-rows/CTA, B split 128 N-rows/CTA (native cg2 semantics).
//     Pure-TMA loads (cta_group::2, complete_tx -> leader barrier), 6 stages.
// ============================================================

#if defined(__CUDA_ARCH_SPECIFIC__) || defined(__CUDA_ARCH_FAMILY_SPECIFIC__) || \
    defined(__CUDA_ARCH_FEAT_SM103_ALL) || defined(__CUDA_ARCH_FEAT_SM100_ALL)
#define USE_TCGEN05 1
#else
#define USE_TCGEN05 0
#endif

#define BM 256            // per cluster pair
#define BN 256
#define BK 32
#define NKIT 32           // 1024 / 32
#define STAGES 6
#define THREADS 256
#define CLUSTER 2

// ---- scratch (static device globals: allowed, no allocation) ----
__device__ float g_xr[8192 * 1024];   // 32 MB, tf32-rounded x
__device__ float g_wr[3072 * 1024];   // 12 MB, tf32-rounded W * mask

// ---- smem layout (bytes); tiles 1024-aligned for SW128 descriptors ----
#define SM_TMEM     0
#define SM_FULL(s)  (16 + (s) * 8)      // leader-side: A+B of both CTAs (64 KB tx)
#define SM_EMPTY(s) (80 + (s) * 8)      // per-CTA: stage recycled
#define SM_FINAL    144
#define SM_A(s)     (1024 + (s) * 16384)     // 128x32 f32 = 16 KB (this CTA's M half)
#define SM_B(s)     (99328 + (s) * 16384)    // 128x32 f32 = 16 KB (this CTA's N half)
#define SM_TOTAL    197632

// idesc kind::tf32 cg2: dtype F32(bit4), atype TF32=2(7-9), btype TF32=2(10-12),
// N/8 @17 (=32), M/16 @24 (=16 for M=256). K-major both.
static constexpr uint32_t IDESC_TF32 =
    (1u << 4) | (2u << 7) | (2u << 10) | ((BN / 8) << 17) | ((BM / 16) << 24);

// SW128 K-major: layout=2, version=1, SBO=64, LBO=1
static constexpr uint64_t DESC_BASE_SW128 =
    (uint64_t(2) << 61) | (uint64_t(1) << 46) | (uint64_t(64) << 32) | (uint64_t(1) << 16);
#define MK_DESC(addr) (DESC_BASE_SW128 | ((uint64_t)((addr) >> 4) & 0x3FFF))

// ---------------- PTX helpers ----------------
static __device__ __forceinline__ uint32_t smem_u32(const void* p) {
    uint32_t a;
    asm("{ .reg .u64 t; cvta.to.shared.u64 t, %1; cvt.u32.u64 %0, t; }" : "=r"(a) : "l"(p));
    return a;
}
static __device__ __forceinline__ uint32_t elect_one() {
    uint32_t p;
    asm volatile("{ .reg .pred p; elect.sync _|p, 0xFFFFFFFF; selp.b32 %0, 1, 0, p; }" : "=r"(p));
    return p;
}
static __device__ __forceinline__ float cvt_tf32(float x) {
    uint32_t r;
    asm("cvt.rna.tf32.f32 %0, %1;" : "=r"(r) : "f"(x));
    return __uint_as_float(r);
}
static __device__ __forceinline__ uint32_t cluster_rank() {
    uint32_t r;
    asm("mov.u32 %0, %%cluster_ctarank;" : "=r"(r));
    return r;
}

#define MBARRIER_INIT(mbar, cnt) \
    asm volatile("mbarrier.init.shared.b64 [%0], %1;" :: "r"((uint32_t)(mbar)), "r"((uint32_t)(cnt)) : "memory")
#define MBARRIER_EXPECT_TX(mbar, tx) \
    asm volatile("mbarrier.arrive.expect_tx.shared.b64 _, [%0], %1;" :: "r"((uint32_t)(mbar)), "r"((uint32_t)(tx)) : "memory")

#define MBARRIER_WAIT_PARITY(mbar_smem_addr, phase_parity) do { \
    uint32_t _mbar = (uint32_t)(mbar_smem_addr); \
    uint32_t _parity = (uint32_t)(phase_parity); \
    uint32_t _done; \
    asm volatile( \
        "{\n\t" \
        ".reg .pred p;\n\t" \
        "mbarrier.try_wait.parity.acquire.cta.shared::cta.b64 p, [%1], %2;\n\t" \
        "selp.b32 %0, 1, 0, p;\n\t" \
        "}" \
        : "=r"(_done) : "r"(_mbar), "r"(_parity) : "memory"); \
    if (!_done) { \
        asm volatile( \
            "{\n\t" \
            ".reg .pred P1;\n\t" \
            "WAIT_LOOP_%=:\n\t" \
            "mbarrier.try_wait.parity.acquire.cta.shared::cta.b64 P1, [%0], %1, 0x989680;\n\t" \
            "@P1 bra.uni WAIT_DONE_%=;\n\t" \
            "bra.uni WAIT_LOOP_%=;\n\t" \
            "WAIT_DONE_%=:\n\t" \
            "}" \
            :: "r"(_mbar), "r"(_parity) : "memory"); \
    } \
} while (0)

// cta_group::2 TMA 2D load: both CTAs execute with local dst; complete_tx
// targets leader CTA's barrier (bit 24 cleared).
#define TMA_2D_CG2(dst, map, cx, cy, mbar) \
    asm volatile( \
        "{\n\t" \
        ".reg .b32 lb;\n\t" \
        "and.b32 lb, %4, 0xFEFFFFFF;\n\t" \
        "cp.async.bulk.tensor.2d.cta_group::2.shared::cluster.global.tile.mbarrier::complete_tx::bytes " \
        "[%0], [%1, {%2, %3}], [lb];\n\t" \
        "}" \
        :: "r"((uint32_t)(dst)), "l"(map), "r"((int)(cx)), "r"((int)(cy)), \
           "r"((uint32_t)(mbar)) : "memory")

#define TCGEN05_ALLOC_CG2(smem_result_addr, nCols) \
    asm volatile("tcgen05.alloc.cta_group::2.sync.aligned.shared::cta.b32 [%0], %1;" \
        :: "r"((uint32_t)(smem_result_addr)), "r"((uint32_t)(nCols)) : "memory")
#define TCGEN05_DEALLOC_CG2(tmem_addr, nCols) \
    asm volatile("tcgen05.dealloc.cta_group::2.sync.aligned.b32 %0, %1;" \
        :: "r"(tmem_addr), "r"((uint32_t)(nCols)))
#define TCGEN05_RELINQUISH_CG2() \
    asm volatile("tcgen05.relinquish_alloc_permit.cta_group::2.sync.aligned;")
#define TCGEN05_COMMIT_MC_CG2(mbar_smem_addr, mask) \
    asm volatile("tcgen05.commit.cta_group::2.mbarrier::arrive::one.shared::cluster.multicast::cluster.b64 [%0], %1;" \
        :: "r"((uint32_t)(mbar_smem_addr)), "h"((uint16_t)(mask)) : "memory")
#define TCGEN05_WAIT_LD() \
    asm volatile("tcgen05.wait::ld.sync.aligned;" ::: "memory")
#define TCGEN05_FENCE_BEFORE() \
    asm volatile("tcgen05.fence::before_thread_sync;" ::: "memory")
#define TCGEN05_FENCE_AFTER() \
    asm volatile("tcgen05.fence::after_thread_sync;" ::: "memory")
#define CLUSTER_SYNC() do { \
    asm volatile("barrier.cluster.arrive.aligned;" ::: "memory"); \
    asm volatile("barrier.cluster.wait.aligned;" ::: "memory"); \
} while (0)

#define TCGEN05_LD_32X32B_X32(r, tmem_addr) \
    asm volatile( \
        "tcgen05.ld.sync.aligned.32x32b.x32.b32 " \
        "{%0, %1, %2, %3, %4, %5, %6, %7, " \
        " %8, %9, %10, %11, %12, %13, %14, %15, " \
        " %16, %17, %18, %19, %20, %21, %22, %23, " \
        " %24, %25, %26, %27, %28, %29, %30, %31}, [%32];" \
        : "=r"((r)[0]),  "=r"((r)[1]),  "=r"((r)[2]),  "=r"((r)[3]), \
          "=r"((r)[4]),  "=r"((r)[5]),  "=r"((r)[6]),  "=r"((r)[7]), \
          "=r"((r)[8]),  "=r"((r)[9]),  "=r"((r)[10]), "=r"((r)[11]), \
          "=r"((r)[12]), "=r"((r)[13]), "=r"((r)[14]), "=r"((r)[15]), \
          "=r"((r)[16]), "=r"((r)[17]), "=r"((r)[18]), "=r"((r)[19]), \
          "=r"((r)[20]), "=r"((r)[21]), "=r"((r)[22]), "=r"((r)[23]), \
          "=r"((r)[24]), "=r"((r)[25]), "=r"((r)[26]), "=r"((r)[27]), \
          "=r"((r)[28]), "=r"((r)[29]), "=r"((r)[30]), "=r"((r)[31]) \
        : "r"(tmem_addr))

// cg2 MMA: 8 disable-lane regs (vs 4 for cg1)
static __device__ __forceinline__ void mma_tf32_cg2(
    uint32_t d_tmem, uint64_t a_desc, uint64_t b_desc, uint32_t idesc, uint32_t en) {
    asm volatile(
        "{\n\t"
        ".reg .pred p;\n\t"
        "setp.ne.u32 p, %5, 0;\n\t"
        "tcgen05.mma.cta_group::2.kind::tf32 [%0], %1, %2, %3, "
        "{%4, %4, %4, %4, %4, %4, %4, %4}, p;\n\t"
        "}"
        :: "r"(d_tmem), "l"(a_desc), "l"(b_desc), "r"(idesc), "r"(0u), "r"(en)
        : "memory");
}

// ---------------- prepass kernels ----------------
__global__ void prep_x_kernel(const float* __restrict__ x) {
    const size_t i = ((size_t)blockIdx.x * blockDim.x + threadIdx.x) * 4;
    float4 v = *reinterpret_cast<const float4*>(x + i);
    v.x = cvt_tf32(v.x); v.y = cvt_tf32(v.y); v.z = cvt_tf32(v.z); v.w = cvt_tf32(v.w);
    *reinterpret_cast<float4*>(g_xr + i) = v;
}

__global__ void prep_w_kernel(const float* __restrict__ W, const float* __restrict__ wv) {
    const float s45  = wv[4] + wv[5];
    const float s23  = wv[2] + wv[3] + s45;
    const float sall = wv[0] + wv[1] + s23;
    const size_t i = ((size_t)blockIdx.x * blockDim.x + threadIdx.x) * 4;  // < 3072*1024
    const int o = (int)(i >> 10);
    const int k = (int)(i & 1023);
    const int ob = (o >= 1536) + (o >= 2304);
    float m;
    if (k >= 768)       m = s45;
    else if (k >= 512)  m = (ob <= 1) ? s23 : s45;
    else                m = (ob == 0) ? sall : (ob == 1 ? s23 : s45);
    float4 v = *reinterpret_cast<const float4*>(W + i);
    v.x = cvt_tf32(v.x * m); v.y = cvt_tf32(v.y * m);
    v.z = cvt_tf32(v.z * m); v.w = cvt_tf32(v.w * m);
    *reinterpret_cast<float4*>(g_wr + i) = v;
}

// ---------------- GEMM kernel ----------------
__global__ void __launch_bounds__(THREADS, 1) __cluster_dims__(CLUSTER, 1, 1)
gemm_tf32_kernel(const float* __restrict__ x, const float* __restrict__ wv,
                 const float* __restrict__ W, const float* __restrict__ bias,
                 float* __restrict__ out,
                 const __grid_constant__ CUtensorMap tmap_a,
                 const __grid_constant__ CUtensorMap tmap_b) {
    const int t = threadIdx.x;
    const int g = blockIdx.x;
#if USE_TCGEN05
    const uint32_t rank = cluster_rank();
    const int c = g >> 1;                        // pair index, [0,384)
    const int n0 = (c % 12) * BN;
    const int m0p = (c / 12) * BM;               // pair's M base
    const int m0 = m0p + (int)rank * 128;        // this CTA's 128 M rows
#else
    const int c = g >> 1;
    const int n0 = (c % 12) * BN;
    const int m0 = (c / 12) * BM + (g & 1) * 128;
#endif

    const float s45  = wv[4] + wv[5];
    const float s23  = wv[2] + wv[3] + s45;
    const float sall = wv[0] + wv[1] + s23;
    const int oband = (n0 >= 1536) + (n0 >= 2304);
    const float bscale = (oband == 0) ? sall : (oband == 1 ? s23 : s45);

#if USE_TCGEN05
    extern __shared__ char smem[];
    const uint32_t sb = smem_u32(smem);
    const int wid = t >> 5;
    const int lid = t & 31;

    if (wid == 0) {
        if (elect_one()) {
#pragma unroll
            for (int s = 0; s < STAGES; ++s) {
                MBARRIER_INIT(sb + SM_FULL(s), 1);       // leader expect_tx arrive
                MBARRIER_INIT(sb + SM_EMPTY(s), 1);      // multicast commit arrive
            }
            MBARRIER_INIT(sb + SM_FINAL, 1);
        }
        TCGEN05_ALLOC_CG2(sb + SM_TMEM, 256);
    }

    // ---- zero-fill mirror tile: this CTA's 128 rows x 256 cols at n0+3072 ----
    {
        float* zt = out + (size_t)m0 * 6144 + n0 + 3072;
        const float4 z = make_float4(0.f, 0.f, 0.f, 0.f);
#pragma unroll
        for (int j = 0; j < 32; ++j) {
            const int idx = t + j * THREADS;     // < 8192
            const int row = idx >> 6, c4 = idx & 63;
            *reinterpret_cast<float4*>(zt + (size_t)row * 6144 + c4 * 4) = z;
        }
    }
    __syncthreads();
    uint32_t tmem;
    asm volatile("ld.shared.b32 %0, [%1];" : "=r"(tmem) : "r"(sb + SM_TMEM));
    CLUSTER_SYNC();   // barriers live in both CTAs before any cg2 TMA / commit

    if (wid == 0) {
        // ---- MMA issuer: leader CTA only ----
        if (rank == 0 && elect_one()) {
            int fph[STAGES] = {0, 0, 0, 0, 0, 0};
#pragma unroll 1
            for (int it = 0; it < NKIT; ++it) {
                const int s = it % STAGES;
                MBARRIER_WAIT_PARITY(sb + SM_FULL(s), fph[s]); fph[s] ^= 1;
                const uint64_t ad = MK_DESC(sb + SM_A(s));
                const uint64_t bd = MK_DESC(sb + SM_B(s));
#pragma unroll
                for (int ks = 0; ks < 4; ++ks)
                    mma_tf32_cg2(tmem, ad + ks * 2, bd + ks * 2, IDESC_TF32,
                                 (uint32_t)(it > 0 || ks > 0));
                TCGEN05_COMMIT_MC_CG2(sb + SM_EMPTY(s), 0x3);
            }
            TCGEN05_COMMIT_MC_CG2(sb + SM_FINAL, 0x3);
        }
    } else if (wid == 1) {
        // ---- TMA producer (both CTAs): A half rows m0.., B half rows n0+rank*128.. ----
        if (elect_one()) {
            const int brow = n0 + (int)rank * 128;
#pragma unroll
            for (int it = 0; it < STAGES; ++it) {
                if (rank == 0) MBARRIER_EXPECT_TX(sb + SM_FULL(it), 65536);
                TMA_2D_CG2(sb + SM_A(it), &tmap_a, it * BK, m0,  sb + SM_FULL(it));
                TMA_2D_CG2(sb + SM_B(it), &tmap_b, it * BK, brow, sb + SM_FULL(it));
            }
            int eph[STAGES] = {0, 0, 0, 0, 0, 0};
#pragma unroll 1
            for (int it = STAGES; it < NKIT; ++it) {
                const int s = it % STAGES;
                MBARRIER_WAIT_PARITY(sb + SM_EMPTY(s), eph[s]); eph[s] ^= 1;
                if (rank == 0) MBARRIER_EXPECT_TX(sb + SM_FULL(s), 65536);
                TMA_2D_CG2(sb + SM_A(s), &tmap_a, it * BK, m0,  sb + SM_FULL(s));
                TMA_2D_CG2(sb + SM_B(s), &tmap_b, it * BK, brow, sb + SM_FULL(s));
            }
        }
    }

    // ---- all threads (both CTAs): wait for all MMAs, epilogue ----
    MBARRIER_WAIT_PARITY(sb + SM_FINAL, 0);
    TCGEN05_FENCE_AFTER();

    // this CTA's TMEM holds its 128 M rows x 256 cols
    const int wg  = wid >> 2;
    const int row = (wid & 3) * 32 + lid;
    float* orow = out + (size_t)(m0 + row) * 6144 + n0;
#pragma unroll
    for (int r4 = 0; r4 < 4; ++r4) {
        const int cb = wg * 128 + r4 * 32;
        uint32_t dr[32];
        TCGEN05_LD_32X32B_X32(dr, tmem + cb);
        TCGEN05_WAIT_LD();
#pragma unroll
        for (int cc = 0; cc < 32; cc += 4) {
            const int col = n0 + cb + cc;
            float4 v;
            v.x = __uint_as_float(dr[cc + 0]) + bias[col + 0] * bscale;
            v.y = __uint_as_float(dr[cc + 1]) + bias[col + 1] * bscale;
            v.z = __uint_as_float(dr[cc + 2]) + bias[col + 2] * bscale;
            v.w = __uint_as_float(dr[cc + 3]) + bias[col + 3] * bscale;
            *reinterpret_cast<float4*>(orow + cb + cc) = v;
        }
    }
    TCGEN05_FENCE_BEFORE();
    __syncthreads();
    if (wid == 0) {
        TCGEN05_RELINQUISH_CG2();
        TCGEN05_DEALLOC_CG2(tmem, 256);
    }
    CLUSTER_SYNC();   // no CTA exits while peer cg2 ops may target its smem
#else
    // SIMT fallback for the family-generic PTX pass (never executed on GB300).
    float mv0, mv1, mv2;
    if (oband == 0)      { mv0 = sall; mv1 = s23; mv2 = s45; }
    else if (oband == 1) { mv0 = s23;  mv1 = s23; mv2 = s45; }
    else                 { mv0 = s45;  mv1 = s45; mv2 = s45; }
    for (int e = t; e < 128 * BN; e += THREADS) {
        const int r = e / BN, cc = e % BN;
        const float* xr = x + (size_t)(m0 + r) * 1024;
        const float* wr = W + (size_t)(n0 + cc) * 1024;
        float acc = 0.f;
        for (int k = 0; k < 1024; ++k) {
            const float m = (k < 512) ? mv0 : (k < 768 ? mv1 : mv2);
            acc += xr[k] * wr[k] * m;
        }
        out[(size_t)(m0 + r) * 6144 + n0 + cc] = acc + bias[n0 + cc] * bscale;
        out[(size_t)(m0 + r) * 6144 + n0 + cc + 3072] = 0.f;
    }
#endif
}

// ---------------- launcher ----------------
typedef CUresult (*PFN_tmap_encode)(
    CUtensorMap*, CUtensorMapDataType, cuuint32_t, void*,
    const cuuint64_t*, const cuuint64_t*, const cuuint32_t*, const cuuint32_t*,
    CUtensorMapInterleave, CUtensorMapSwizzle, CUtensorMapL2promotion,
    CUtensorMapFloatOOBfill);

static void make_tmap(CUtensorMap* tm, void* base, cuuint64_t rows) {
    PFN_tmap_encode enc = nullptr;
    cudaDriverEntryPointQueryResult st;
    cudaGetDriverEntryPointByVersion("cuTensorMapEncodeTiled", (void**)&enc,
                                     12000, cudaEnableDefault, &st);
    cuuint64_t dims[2]    = {1024, rows};
    cuuint64_t strides[1] = {1024 * sizeof(float)};
    cuuint32_t box[2]     = {BK, 128};
    cuuint32_t estr[2]    = {1, 1};
    enc(tm, CU_TENSOR_MAP_DATA_TYPE_FLOAT32, 2, base,
        dims, strides, box, estr,
        CU_TENSOR_MAP_INTERLEAVE_NONE, CU_TENSOR_MAP_SWIZZLE_128B,
        CU_TENSOR_MAP_L2_PROMOTION_L2_128B, CU_TENSOR_MAP_FLOAT_OOB_FILL_NONE);
}

extern "C" void kernel_launch(void* const* d_in, const int* in_sizes, int n_in,
                              void* d_out, int out_size) {
    const float *x = nullptr, *wv = nullptr, *W = nullptr, *b = nullptr;
    for (int i = 0; i < n_in; ++i) {
        switch (in_sizes[i]) {
            case 8388608: x  = (const float*)d_in[i]; break;
            case 6:       wv = (const float*)d_in[i]; break;
            case 6291456: W  = (const float*)d_in[i]; break;
            case 6144:    b  = (const float*)d_in[i]; break;
        }
    }
    if (!x)  x  = (const float*)d_in[0];
    if (!wv) wv = (const float*)d_in[1];
    if (!W)  W  = (const float*)d_in[2];
    if (!b)  b  = (const float*)d_in[3];
    float* out = (float*)d_out;

    void* xr_ptr = nullptr; void* wr_ptr = nullptr;
    cudaGetSymbolAddress(&xr_ptr, g_xr);
    cudaGetSymbolAddress(&wr_ptr, g_wr);
    CUtensorMap tmap_a, tmap_b;
    make_tmap(&tmap_a, xr_ptr, 8192);
    make_tmap(&tmap_b, wr_ptr, 3072);

    cudaFuncSetAttribute(gemm_tf32_kernel,
                         cudaFuncAttributeMaxDynamicSharedMemorySize, SM_TOTAL);

    prep_x_kernel<<<8192, 256>>>(x);
    prep_w_kernel<<<3072, 256>>>(W, wv);
    gemm_tf32_kernel<<<768, THREADS, SM_TOTAL>>>(x, wv, W, b, out, tmap_a, tmap_b);
}

// round 10
// speedup vs baseline: 1.2263x; 1.1300x over previous
#include <cuda_runtime.h>
#include <cuda.h>
#include <cstdint>

// ============================================================
// MixedLinearV2 = GEMM out[8192,6144] = x[8192,1024] @ (W*M)^T + b*rowmask
//   M == 0 for o >= 3072 -> GEMM over o in [0,3072), zero-fill mirror inline.
// R6: PERSISTENT cg2 tcgen05 tf32 GEMM. 74 pairs (148 CTAs), each pair loops
//     over tiles; K pipeline never drains; TMEM D double-buffered so epilogue
//     (warps 4-7) overlaps next tile's MMAs; warps 2-3 zero the dead mirror.
// ============================================================

#if defined(__CUDA_ARCH_SPECIFIC__) || defined(__CUDA_ARCH_FAMILY_SPECIFIC__) || \
    defined(__CUDA_ARCH_FEAT_SM103_ALL) || defined(__CUDA_ARCH_FEAT_SM100_ALL)
#define USE_TCGEN05 1
#else
#define USE_TCGEN05 0
#endif

#define BM 256            // per cluster pair
#define BN 256
#define BK 32
#define NKIT 32           // 1024 / 32
#define STAGES 6
#define THREADS 256
#define CLUSTER 2
#define PAIRS 74
#define NTILES 384        // 12 (n) x 32 (m-pairs)

// ---- scratch (static device globals: allowed, no allocation) ----
__device__ float g_xr[8192 * 1024];   // 32 MB, tf32-rounded x
__device__ float g_wr[3072 * 1024];   // 12 MB, tf32-rounded W * mask

// ---- smem layout (bytes); tiles 1024-aligned for SW128 descriptors ----
#define SM_TMEM       0
#define SM_FULL(s)    (16 + (s) * 8)       // leader: A+B tx of both CTAs (64 KB)
#define SM_EMPTY(s)   (80 + (s) * 8)       // per-CTA: K-stage recycled
#define SM_EPI_FULL(b)  (144 + (b) * 8)    // per-CTA: D[b] ready
#define SM_EPI_EMPTY(b) (160 + (b) * 8)    // leader: D[b] drained by both CTAs
#define SM_A(s)       (1024 + (s) * 16384)   // 128x32 f32 = 16 KB
#define SM_B(s)       (99328 + (s) * 16384)  // 128x32 f32 = 16 KB
#define SM_TOTAL      197632

// idesc kind::tf32 cg2: dtype F32(bit4), atype TF32=2(7-9), btype TF32=2(10-12),
// N/8 @17 (=32), M/16 @24 (=16 for M=256). K-major both.
static constexpr uint32_t IDESC_TF32 =
    (1u << 4) | (2u << 7) | (2u << 10) | ((BN / 8) << 17) | ((BM / 16) << 24);

// SW128 K-major: layout=2, version=1, SBO=64, LBO=1
static constexpr uint64_t DESC_BASE_SW128 =
    (uint64_t(2) << 61) | (uint64_t(1) << 46) | (uint64_t(64) << 32) | (uint64_t(1) << 16);
#define MK_DESC(addr) (DESC_BASE_SW128 | ((uint64_t)((addr) >> 4) & 0x3FFF))

// ---------------- PTX helpers ----------------
static __device__ __forceinline__ uint32_t smem_u32(const void* p) {
    uint32_t a;
    asm("{ .reg .u64 t; cvta.to.shared.u64 t, %1; cvt.u32.u64 %0, t; }" : "=r"(a) : "l"(p));
    return a;
}
static __device__ __forceinline__ uint32_t elect_one() {
    uint32_t p;
    asm volatile("{ .reg .pred p; elect.sync _|p, 0xFFFFFFFF; selp.b32 %0, 1, 0, p; }" : "=r"(p));
    return p;
}
static __device__ __forceinline__ float cvt_tf32(float x) {
    uint32_t r;
    asm("cvt.rna.tf32.f32 %0, %1;" : "=r"(r) : "f"(x));
    return __uint_as_float(r);
}
static __device__ __forceinline__ uint32_t cluster_rank() {
    uint32_t r;
    asm("mov.u32 %0, %%cluster_ctarank;" : "=r"(r));
    return r;
}

#define MBARRIER_INIT(mbar, cnt) \
    asm volatile("mbarrier.init.shared.b64 [%0], %1;" :: "r"((uint32_t)(mbar)), "r"((uint32_t)(cnt)) : "memory")
#define MBARRIER_EXPECT_TX(mbar, tx) \
    asm volatile("mbarrier.arrive.expect_tx.shared.b64 _, [%0], %1;" :: "r"((uint32_t)(mbar)), "r"((uint32_t)(tx)) : "memory")
// arrive on the pair-leader's barrier (clear Sm100MmaPeerBit, bit 24)
#define MBARRIER_ARRIVE_LEADER(mbar) \
    asm volatile( \
        "{\n\t.reg .b32 la;\n\tand.b32 la, %0, 0xFEFFFFFF;\n\t" \
        "mbarrier.arrive.release.cluster.shared::cluster.b64 _, [la];\n\t}" \
        :: "r"((uint32_t)(mbar)) : "memory")

#define MBARRIER_WAIT_PARITY(mbar_smem_addr, phase_parity) do { \
    uint32_t _mbar = (uint32_t)(mbar_smem_addr); \
    uint32_t _parity = (uint32_t)(phase_parity); \
    uint32_t _done; \
    asm volatile( \
        "{\n\t" \
        ".reg .pred p;\n\t" \
        "mbarrier.try_wait.parity.acquire.cta.shared::cta.b64 p, [%1], %2;\n\t" \
        "selp.b32 %0, 1, 0, p;\n\t" \
        "}" \
        : "=r"(_done) : "r"(_mbar), "r"(_parity) : "memory"); \
    if (!_done) { \
        asm volatile( \
            "{\n\t" \
            ".reg .pred P1;\n\t" \
            "WAIT_LOOP_%=:\n\t" \
            "mbarrier.try_wait.parity.acquire.cta.shared::cta.b64 P1, [%0], %1, 0x989680;\n\t" \
            "@P1 bra.uni WAIT_DONE_%=;\n\t" \
            "bra.uni WAIT_LOOP_%=;\n\t" \
            "WAIT_DONE_%=:\n\t" \
            "}" \
            :: "r"(_mbar), "r"(_parity) : "memory"); \
    } \
} while (0)

// cta_group::2 TMA 2D load: both CTAs execute with local dst; complete_tx
// targets leader CTA's barrier (bit 24 cleared).
#define TMA_2D_CG2(dst, map, cx, cy, mbar) \
    asm volatile( \
        "{\n\t" \
        ".reg .b32 lb;\n\t" \
        "and.b32 lb, %4, 0xFEFFFFFF;\n\t" \
        "cp.async.bulk.tensor.2d.cta_group::2.shared::cluster.global.tile.mbarrier::complete_tx::bytes " \
        "[%0], [%1, {%2, %3}], [lb];\n\t" \
        "}" \
        :: "r"((uint32_t)(dst)), "l"(map), "r"((int)(cx)), "r"((int)(cy)), \
           "r"((uint32_t)(mbar)) : "memory")

#define TCGEN05_ALLOC_CG2(smem_result_addr, nCols) \
    asm volatile("tcgen05.alloc.cta_group::2.sync.aligned.shared::cta.b32 [%0], %1;" \
        :: "r"((uint32_t)(smem_result_addr)), "r"((uint32_t)(nCols)) : "memory")
#define TCGEN05_DEALLOC_CG2(tmem_addr, nCols) \
    asm volatile("tcgen05.dealloc.cta_group::2.sync.aligned.b32 %0, %1;" \
        :: "r"(tmem_addr), "r"((uint32_t)(nCols)))
#define TCGEN05_RELINQUISH_CG2() \
    asm volatile("tcgen05.relinquish_alloc_permit.cta_group::2.sync.aligned;")
#define TCGEN05_COMMIT_MC_CG2(mbar_smem_addr, mask) \
    asm volatile("tcgen05.commit.cta_group::2.mbarrier::arrive::one.shared::cluster.multicast::cluster.b64 [%0], %1;" \
        :: "r"((uint32_t)(mbar_smem_addr)), "h"((uint16_t)(mask)) : "memory")
#define TCGEN05_WAIT_LD() \
    asm volatile("tcgen05.wait::ld.sync.aligned;" ::: "memory")
#define TCGEN05_FENCE_BEFORE() \
    asm volatile("tcgen05.fence::before_thread_sync;" ::: "memory")
#define TCGEN05_FENCE_AFTER() \
    asm volatile("tcgen05.fence::after_thread_sync;" ::: "memory")
#define CLUSTER_SYNC() do { \
    asm volatile("barrier.cluster.arrive.aligned;" ::: "memory"); \
    asm volatile("barrier.cluster.wait.aligned;" ::: "memory"); \
} while (0)

#define TCGEN05_LD_32X32B_X32(r, tmem_addr) \
    asm volatile( \
        "tcgen05.ld.sync.aligned.32x32b.x32.b32 " \
        "{%0, %1, %2, %3, %4, %5, %6, %7, " \
        " %8, %9, %10, %11, %12, %13, %14, %15, " \
        " %16, %17, %18, %19, %20, %21, %22, %23, " \
        " %24, %25, %26, %27, %28, %29, %30, %31}, [%32];" \
        : "=r"((r)[0]),  "=r"((r)[1]),  "=r"((r)[2]),  "=r"((r)[3]), \
          "=r"((r)[4]),  "=r"((r)[5]),  "=r"((r)[6]),  "=r"((r)[7]), \
          "=r"((r)[8]),  "=r"((r)[9]),  "=r"((r)[10]), "=r"((r)[11]), \
          "=r"((r)[12]), "=r"((r)[13]), "=r"((r)[14]), "=r"((r)[15]), \
          "=r"((r)[16]), "=r"((r)[17]), "=r"((r)[18]), "=r"((r)[19]), \
          "=r"((r)[20]), "=r"((r)[21]), "=r"((r)[22]), "=r"((r)[23]), \
          "=r"((r)[24]), "=r"((r)[25]), "=r"((r)[26]), "=r"((r)[27]), \
          "=r"((r)[28]), "=r"((r)[29]), "=r"((r)[30]), "=r"((r)[31]) \
        : "r"(tmem_addr))

// cg2 MMA: 8 disable-lane regs
static __device__ __forceinline__ void mma_tf32_cg2(
    uint32_t d_tmem, uint64_t a_desc, uint64_t b_desc, uint32_t idesc, uint32_t en) {
    asm volatile(
        "{\n\t"
        ".reg .pred p;\n\t"
        "setp.ne.u32 p, %5, 0;\n\t"
        "tcgen05.mma.cta_group::2.kind::tf32 [%0], %1, %2, %3, "
        "{%4, %4, %4, %4, %4, %4, %4, %4}, p;\n\t"
        "}"
        :: "r"(d_tmem), "l"(a_desc), "l"(b_desc), "r"(idesc), "r"(0u), "r"(en)
        : "memory");
}

// ---------------- prepass kernels ----------------
__global__ void prep_x_kernel(const float* __restrict__ x) {
    const size_t i = ((size_t)blockIdx.x * blockDim.x + threadIdx.x) * 4;
    float4 v = *reinterpret_cast<const float4*>(x + i);
    v.x = cvt_tf32(v.x); v.y = cvt_tf32(v.y); v.z = cvt_tf32(v.z); v.w = cvt_tf32(v.w);
    *reinterpret_cast<float4*>(g_xr + i) = v;
}

__global__ void prep_w_kernel(const float* __restrict__ W, const float* __restrict__ wv) {
    const float s45  = wv[4] + wv[5];
    const float s23  = wv[2] + wv[3] + s45;
    const float sall = wv[0] + wv[1] + s23;
    const size_t i = ((size_t)blockIdx.x * blockDim.x + threadIdx.x) * 4;  // < 3072*1024
    const int o = (int)(i >> 10);
    const int k = (int)(i & 1023);
    const int ob = (o >= 1536) + (o >= 2304);
    float m;
    if (k >= 768)       m = s45;
    else if (k >= 512)  m = (ob <= 1) ? s23 : s45;
    else                m = (ob == 0) ? sall : (ob == 1 ? s23 : s45);
    float4 v = *reinterpret_cast<const float4*>(W + i);
    v.x = cvt_tf32(v.x * m); v.y = cvt_tf32(v.y * m);
    v.z = cvt_tf32(v.z * m); v.w = cvt_tf32(v.w * m);
    *reinterpret_cast<float4*>(g_wr + i) = v;
}

// ---------------- persistent GEMM kernel ----------------
__global__ void __launch_bounds__(THREADS, 1) __cluster_dims__(CLUSTER, 1, 1)
gemm_tf32_kernel(const float* __restrict__ x, const float* __restrict__ wv,
                 const float* __restrict__ W, const float* __restrict__ bias,
                 float* __restrict__ out,
                 const __grid_constant__ CUtensorMap tmap_a,
                 const __grid_constant__ CUtensorMap tmap_b) {
    const int t = threadIdx.x;
    const int pair = blockIdx.x >> 1;

    const float s45  = wv[4] + wv[5];
    const float s23  = wv[2] + wv[3] + s45;
    const float sall = wv[0] + wv[1] + s23;

#if USE_TCGEN05
    const uint32_t rank = cluster_rank();
    extern __shared__ char smem[];
    const uint32_t sb = smem_u32(smem);
    const int wid = t >> 5;
    const int lid = t & 31;

    if (wid == 0) {
        if (elect_one()) {
#pragma unroll
            for (int s = 0; s < STAGES; ++s) {
                MBARRIER_INIT(sb + SM_FULL(s), 1);
                MBARRIER_INIT(sb + SM_EMPTY(s), 1);
            }
#pragma unroll
            for (int b2 = 0; b2 < 2; ++b2) {
                MBARRIER_INIT(sb + SM_EPI_FULL(b2), 1);
                MBARRIER_INIT(sb + SM_EPI_EMPTY(b2), 2);
            }
        }
        TCGEN05_ALLOC_CG2(sb + SM_TMEM, 512);
    }
    __syncthreads();
    uint32_t tmem;
    asm volatile("ld.shared.b32 %0, [%1];" : "=r"(tmem) : "r"(sb + SM_TMEM));
    CLUSTER_SYNC();   // barriers live in both CTAs before any cg2 TMA / commit

    if (wid == 0) {
        // ================= MMA issuer (leader CTA only) =================
        if (rank == 0 && elect_one()) {
            int fph[STAGES] = {0, 0, 0, 0, 0, 0};
            int eph2[2] = {0, 0};
            int kg = 0, lt = 0;
#pragma unroll 1
            for (int tile = pair; tile < NTILES; tile += PAIRS, ++lt) {
                const int buf = lt & 1;
                const uint32_t dmem = tmem + buf * 256;
                if (lt >= 2) {
                    MBARRIER_WAIT_PARITY(sb + SM_EPI_EMPTY(buf), eph2[buf]);
                    eph2[buf] ^= 1;
                }
#pragma unroll 1
                for (int it = 0; it < NKIT; ++it, ++kg) {
                    const int s = kg % STAGES;
                    MBARRIER_WAIT_PARITY(sb + SM_FULL(s), fph[s]); fph[s] ^= 1;
                    const uint64_t ad = MK_DESC(sb + SM_A(s));
                    const uint64_t bd = MK_DESC(sb + SM_B(s));
#pragma unroll
                    for (int ks = 0; ks < 4; ++ks)
                        mma_tf32_cg2(dmem, ad + ks * 2, bd + ks * 2, IDESC_TF32,
                                     (uint32_t)(it > 0 || ks > 0));
                    TCGEN05_COMMIT_MC_CG2(sb + SM_EMPTY(s), 0x3);
                }
                TCGEN05_COMMIT_MC_CG2(sb + SM_EPI_FULL(buf), 0x3);
            }
        }
    } else if (wid == 1) {
        // ================= TMA producer (both CTAs) =================
        if (elect_one()) {
            int eph[STAGES] = {0, 0, 0, 0, 0, 0};
            int kg = 0;
#pragma unroll 1
            for (int tile = pair; tile < NTILES; tile += PAIRS) {
                const int m0 = (tile / 12) * BM + (int)rank * 128;
                const int brow = (tile % 12) * BN + (int)rank * 128;
#pragma unroll 1
                for (int it = 0; it < NKIT; ++it, ++kg) {
                    const int s = kg % STAGES;
                    if (kg >= STAGES) {
                        MBARRIER_WAIT_PARITY(sb + SM_EMPTY(s), eph[s]); eph[s] ^= 1;
                    }
                    if (rank == 0) MBARRIER_EXPECT_TX(sb + SM_FULL(s), 65536);
                    TMA_2D_CG2(sb + SM_A(s), &tmap_a, it * BK, m0,   sb + SM_FULL(s));
                    TMA_2D_CG2(sb + SM_B(s), &tmap_b, it * BK, brow, sb + SM_FULL(s));
                }
            }
        }
    } else if (wid < 4) {
        // ================= zero-fill mirror tiles (warps 2-3) =================
        const int p2 = t - 64;   // 0..63
        const float4 z = make_float4(0.f, 0.f, 0.f, 0.f);
#pragma unroll 1
        for (int tile = pair; tile < NTILES; tile += PAIRS) {
            const int m0 = (tile / 12) * BM + (int)rank * 128;
            const int n0z = (tile % 12) * BN + 3072;
            float* zt = out + (size_t)m0 * 6144 + n0z;
#pragma unroll 4
            for (int j = 0; j < 128; ++j) {
                const int idx = p2 + j * 64;      // < 8192
                const int row = idx >> 6, c4 = idx & 63;
                *reinterpret_cast<float4*>(zt + (size_t)row * 6144 + c4 * 4) = z;
            }
        }
    } else {
        // ================= epilogue (warps 4-7, both CTAs) =================
        const int row = (wid - 4) * 32 + lid;
        int fphE[2] = {0, 0};
        int lt = 0;
#pragma unroll 1
        for (int tile = pair; tile < NTILES; tile += PAIRS, ++lt) {
            const int buf = lt & 1;
            const uint32_t dmem = tmem + buf * 256;
            const int n0 = (tile % 12) * BN;
            const int m0 = (tile / 12) * BM + (int)rank * 128;
            const int oband = (n0 >= 1536) + (n0 >= 2304);
            const float bscale = (oband == 0) ? sall : (oband == 1 ? s23 : s45);

            MBARRIER_WAIT_PARITY(sb + SM_EPI_FULL(buf), fphE[buf]); fphE[buf] ^= 1;
            TCGEN05_FENCE_AFTER();

            float* orow = out + (size_t)(m0 + row) * 6144 + n0;
#pragma unroll
            for (int cb = 0; cb < 256; cb += 32) {
                uint32_t dr[32];
                TCGEN05_LD_32X32B_X32(dr, dmem + cb);
                TCGEN05_WAIT_LD();
#pragma unroll
                for (int cc = 0; cc < 32; cc += 4) {
                    const int col = n0 + cb + cc;
                    float4 v;
                    v.x = __uint_as_float(dr[cc + 0]) + bias[col + 0] * bscale;
                    v.y = __uint_as_float(dr[cc + 1]) + bias[col + 1] * bscale;
                    v.z = __uint_as_float(dr[cc + 2]) + bias[col + 2] * bscale;
                    v.w = __uint_as_float(dr[cc + 3]) + bias[col + 3] * bscale;
                    *reinterpret_cast<float4*>(orow + cb + cc) = v;
                }
            }
            TCGEN05_FENCE_BEFORE();
            asm volatile("bar.sync 14, 128;" ::: "memory");   // warps 4-7
            if (wid == 4 && elect_one())
                MBARRIER_ARRIVE_LEADER(sb + SM_EPI_EMPTY(buf));
        }
    }

    __syncthreads();
    if (wid == 0) {
        TCGEN05_RELINQUISH_CG2();
        TCGEN05_DEALLOC_CG2(tmem, 512);
    }
    CLUSTER_SYNC();   // no CTA exits while peer cg2 ops may target its smem
#else
    // SIMT fallback for the family-generic PTX pass (never executed on GB300).
    const int rankf = blockIdx.x & 1;
    for (int tile = pair; tile < NTILES; tile += PAIRS) {
        const int n0 = (tile % 12) * BN;
        const int m0 = (tile / 12) * BM + rankf * 128;
        const int oband = (n0 >= 1536) + (n0 >= 2304);
        const float bscale = (oband == 0) ? sall : (oband == 1 ? s23 : s45);
        float mv0, mv1, mv2;
        if (oband == 0)      { mv0 = sall; mv1 = s23; mv2 = s45; }
        else if (oband == 1) { mv0 = s23;  mv1 = s23; mv2 = s45; }
        else                 { mv0 = s45;  mv1 = s45; mv2 = s45; }
        for (int e = t; e < 128 * BN; e += THREADS) {
            const int r = e / BN, cc = e % BN;
            const float* xr = x + (size_t)(m0 + r) * 1024;
            const float* wr = W + (size_t)(n0 + cc) * 1024;
            float acc = 0.f;
            for (int k = 0; k < 1024; ++k) {
                const float m = (k < 512) ? mv0 : (k < 768 ? mv1 : mv2);
                acc += xr[k] * wr[k] * m;
            }
            out[(size_t)(m0 + r) * 6144 + n0 + cc] = acc + bias[n0 + cc] * bscale;
            out[(size_t)(m0 + r) * 6144 + n0 + cc + 3072] = 0.f;
        }
    }
#endif
}

// ---------------- launcher ----------------
typedef CUresult (*PFN_tmap_encode)(
    CUtensorMap*, CUtensorMapDataType, cuuint32_t, void*,
    const cuuint64_t*, const cuuint64_t*, const cuuint32_t*, const cuuint32_t*,
    CUtensorMapInterleave, CUtensorMapSwizzle, CUtensorMapL2promotion,
    CUtensorMapFloatOOBfill);

static void make_tmap(CUtensorMap* tm, void* base, cuuint64_t rows) {
    PFN_tmap_encode enc = nullptr;
    cudaDriverEntryPointQueryResult st;
    cudaGetDriverEntryPointByVersion("cuTensorMapEncodeTiled", (void**)&enc,
                                     12000, cudaEnableDefault, &st);
    cuuint64_t dims[2]    = {1024, rows};
    cuuint64_t strides[1] = {1024 * sizeof(float)};
    cuuint32_t box[2]     = {BK, 128};
    cuuint32_t estr[2]    = {1, 1};
    enc(tm, CU_TENSOR_MAP_DATA_TYPE_FLOAT32, 2, base,
        dims, strides, box, estr,
        CU_TENSOR_MAP_INTERLEAVE_NONE, CU_TENSOR_MAP_SWIZZLE_128B,
        CU_TENSOR_MAP_L2_PROMOTION_L2_128B, CU_TENSOR_MAP_FLOAT_OOB_FILL_NONE);
}

extern "C" void kernel_launch(void* const* d_in, const int* in_sizes, int n_in,
                              void* d_out, int out_size) {
    const float *x = nullptr, *wv = nullptr, *W = nullptr, *b = nullptr;
    for (int i = 0; i < n_in; ++i) {
        switch (in_sizes[i]) {
            case 8388608: x  = (const float*)d_in[i]; break;
            case 6:       wv = (const float*)d_in[i]; break;
            case 6291456: W  = (const float*)d_in[i]; break;
            case 6144:    b  = (const float*)d_in[i]; break;
        }
    }
    if (!x)  x  = (const float*)d_in[0];
    if (!wv) wv = (const float*)d_in[1];
    if (!W)  W  = (const float*)d_in[2];
    if (!b)  b  = (const float*)d_in[3];
    float* out = (float*)d_out;

    void* xr_ptr = nullptr; void* wr_ptr = nullptr;
    cudaGetSymbolAddress(&xr_ptr, g_xr);
    cudaGetSymbolAddress(&wr_ptr, g_wr);
    CUtensorMap tmap_a, tmap_b;
    make_tmap(&tmap_a, xr_ptr, 8192);
    make_tmap(&tmap_b, wr_ptr, 3072);

    cudaFuncSetAttribute(gemm_tf32_kernel,
                         cudaFuncAttributeMaxDynamicSharedMemorySize, SM_TOTAL);

    prep_x_kernel<<<8192, 256>>>(x);
    prep_w_kernel<<<3072, 256>>>(W, wv);
    gemm_tf32_kernel<<<PAIRS * CLUSTER, THREADS, SM_TOTAL>>>(x, wv, W, b, out,
                                                             tmap_a, tmap_b);
}

// round 14
// speedup vs baseline: 1.2466x; 1.0165x over previous
#include <cuda_runtime.h>
#include <cuda.h>
#include <cstdint>

// ============================================================
// MixedLinearV2 = GEMM out[8192,6144] = x[8192,1024] @ (W*M)^T + b*rowmask
//   M == 0 for o >= 3072 -> GEMM over o in [0,3072), zero-fill mirror inline.
// R7: R6 persistent cg2 scheme + PERFECT BALANCE: 64 pairs x exactly 6 tiles
//     (384 = 64*6), fused prepass kernel (x-round + W-mask-round in one launch).
// ============================================================

#if defined(__CUDA_ARCH_SPECIFIC__) || defined(__CUDA_ARCH_FAMILY_SPECIFIC__) || \
    defined(__CUDA_ARCH_FEAT_SM103_ALL) || defined(__CUDA_ARCH_FEAT_SM100_ALL)
#define USE_TCGEN05 1
#else
#define USE_TCGEN05 0
#endif

#define BM 256            // per cluster pair
#define BN 256
#define BK 32
#define NKIT 32           // 1024 / 32
#define STAGES 6
#define THREADS 256
#define CLUSTER 2
#define PAIRS 64          // 384 tiles = 64 pairs x 6 tiles, perfectly balanced
#define NTILES 384        // 12 (n) x 32 (m-pairs)

// ---- scratch (static device globals: allowed, no allocation) ----
__device__ float g_xr[8192 * 1024];   // 32 MB, tf32-rounded x
__device__ float g_wr[3072 * 1024];   // 12 MB, tf32-rounded W * mask

// ---- smem layout (bytes); tiles 1024-aligned for SW128 descriptors ----
#define SM_TMEM       0
#define SM_FULL(s)    (16 + (s) * 8)       // leader: A+B tx of both CTAs (64 KB)
#define SM_EMPTY(s)   (80 + (s) * 8)       // per-CTA: K-stage recycled
#define SM_EPI_FULL(b)  (144 + (b) * 8)    // per-CTA: D[b] ready
#define SM_EPI_EMPTY(b) (160 + (b) * 8)    // leader: D[b] drained by both CTAs
#define SM_A(s)       (1024 + (s) * 16384)   // 128x32 f32 = 16 KB
#define SM_B(s)       (99328 + (s) * 16384)  // 128x32 f32 = 16 KB
#define SM_TOTAL      197632

// idesc kind::tf32 cg2: dtype F32(bit4), atype TF32=2(7-9), btype TF32=2(10-12),
// N/8 @17 (=32), M/16 @24 (=16 for M=256). K-major both.
static constexpr uint32_t IDESC_TF32 =
    (1u << 4) | (2u << 7) | (2u << 10) | ((BN / 8) << 17) | ((BM / 16) << 24);

// SW128 K-major: layout=2, version=1, SBO=64, LBO=1
static constexpr uint64_t DESC_BASE_SW128 =
    (uint64_t(2) << 61) | (uint64_t(1) << 46) | (uint64_t(64) << 32) | (uint64_t(1) << 16);
#define MK_DESC(addr) (DESC_BASE_SW128 | ((uint64_t)((addr) >> 4) & 0x3FFF))

// ---------------- PTX helpers ----------------
static __device__ __forceinline__ uint32_t smem_u32(const void* p) {
    uint32_t a;
    asm("{ .reg .u64 t; cvta.to.shared.u64 t, %1; cvt.u32.u64 %0, t; }" : "=r"(a) : "l"(p));
    return a;
}
static __device__ __forceinline__ uint32_t elect_one() {
    uint32_t p;
    asm volatile("{ .reg .pred p; elect.sync _|p, 0xFFFFFFFF; selp.b32 %0, 1, 0, p; }" : "=r"(p));
    return p;
}
static __device__ __forceinline__ float cvt_tf32(float x) {
    uint32_t r;
    asm("cvt.rna.tf32.f32 %0, %1;" : "=r"(r) : "f"(x));
    return __uint_as_float(r);
}
static __device__ __forceinline__ uint32_t cluster_rank() {
    uint32_t r;
    asm("mov.u32 %0, %%cluster_ctarank;" : "=r"(r));
    return r;
}

#define MBARRIER_INIT(mbar, cnt) \
    asm volatile("mbarrier.init.shared.b64 [%0], %1;" :: "r"((uint32_t)(mbar)), "r"((uint32_t)(cnt)) : "memory")
#define MBARRIER_EXPECT_TX(mbar, tx) \
    asm volatile("mbarrier.arrive.expect_tx.shared.b64 _, [%0], %1;" :: "r"((uint32_t)(mbar)), "r"((uint32_t)(tx)) : "memory")
// arrive on the pair-leader's barrier (clear Sm100MmaPeerBit, bit 24)
#define MBARRIER_ARRIVE_LEADER(mbar) \
    asm volatile( \
        "{\n\t.reg .b32 la;\n\tand.b32 la, %0, 0xFEFFFFFF;\n\t" \
        "mbarrier.arrive.release.cluster.shared::cluster.b64 _, [la];\n\t}" \
        :: "r"((uint32_t)(mbar)) : "memory")

#define MBARRIER_WAIT_PARITY(mbar_smem_addr, phase_parity) do { \
    uint32_t _mbar = (uint32_t)(mbar_smem_addr); \
    uint32_t _parity = (uint32_t)(phase_parity); \
    uint32_t _done; \
    asm volatile( \
        "{\n\t" \
        ".reg .pred p;\n\t" \
        "mbarrier.try_wait.parity.acquire.cta.shared::cta.b64 p, [%1], %2;\n\t" \
        "selp.b32 %0, 1, 0, p;\n\t" \
        "}" \
        : "=r"(_done) : "r"(_mbar), "r"(_parity) : "memory"); \
    if (!_done) { \
        asm volatile( \
            "{\n\t" \
            ".reg .pred P1;\n\t" \
            "WAIT_LOOP_%=:\n\t" \
            "mbarrier.try_wait.parity.acquire.cta.shared::cta.b64 P1, [%0], %1, 0x989680;\n\t" \
            "@P1 bra.uni WAIT_DONE_%=;\n\t" \
            "bra.uni WAIT_LOOP_%=;\n\t" \
            "WAIT_DONE_%=:\n\t" \
            "}" \
            :: "r"(_mbar), "r"(_parity) : "memory"); \
    } \
} while (0)

// cta_group::2 TMA 2D load: both CTAs execute with local dst; complete_tx
// targets leader CTA's barrier (bit 24 cleared).
#define TMA_2D_CG2(dst, map, cx, cy, mbar) \
    asm volatile( \
        "{\n\t" \
        ".reg .b32 lb;\n\t" \
        "and.b32 lb, %4, 0xFEFFFFFF;\n\t" \
        "cp.async.bulk.tensor.2d.cta_group::2.shared::cluster.global.tile.mbarrier::complete_tx::bytes " \
        "[%0], [%1, {%2, %3}], [lb];\n\t" \
        "}" \
        :: "r"((uint32_t)(dst)), "l"(map), "r"((int)(cx)), "r"((int)(cy)), \
           "r"((uint32_t)(mbar)) : "memory")

#define TCGEN05_ALLOC_CG2(smem_result_addr, nCols) \
    asm volatile("tcgen05.alloc.cta_group::2.sync.aligned.shared::cta.b32 [%0], %1;" \
        :: "r"((uint32_t)(smem_result_addr)), "r"((uint32_t)(nCols)) : "memory")
#define TCGEN05_DEALLOC_CG2(tmem_addr, nCols) \
    asm volatile("tcgen05.dealloc.cta_group::2.sync.aligned.b32 %0, %1;" \
        :: "r"(tmem_addr), "r"((uint32_t)(nCols)))
#define TCGEN05_RELINQUISH_CG2() \
    asm volatile("tcgen05.relinquish_alloc_permit.cta_group::2.sync.aligned;")
#define TCGEN05_COMMIT_MC_CG2(mbar_smem_addr, mask) \
    asm volatile("tcgen05.commit.cta_group::2.mbarrier::arrive::one.shared::cluster.multicast::cluster.b64 [%0], %1;" \
        :: "r"((uint32_t)(mbar_smem_addr)), "h"((uint16_t)(mask)) : "memory")
#define TCGEN05_WAIT_LD() \
    asm volatile("tcgen05.wait::ld.sync.aligned;" ::: "memory")
#define TCGEN05_FENCE_BEFORE() \
    asm volatile("tcgen05.fence::before_thread_sync;" ::: "memory")
#define TCGEN05_FENCE_AFTER() \
    asm volatile("tcgen05.fence::after_thread_sync;" ::: "memory")
#define CLUSTER_SYNC() do { \
    asm volatile("barrier.cluster.arrive.aligned;" ::: "memory"); \
    asm volatile("barrier.cluster.wait.aligned;" ::: "memory"); \
} while (0)

#define TCGEN05_LD_32X32B_X32(r, tmem_addr) \
    asm volatile( \
        "tcgen05.ld.sync.aligned.32x32b.x32.b32 " \
        "{%0, %1, %2, %3, %4, %5, %6, %7, " \
        " %8, %9, %10, %11, %12, %13, %14, %15, " \
        " %16, %17, %18, %19, %20, %21, %22, %23, " \
        " %24, %25, %26, %27, %28, %29, %30, %31}, [%32];" \
        : "=r"((r)[0]),  "=r"((r)[1]),  "=r"((r)[2]),  "=r"((r)[3]), \
          "=r"((r)[4]),  "=r"((r)[5]),  "=r"((r)[6]),  "=r"((r)[7]), \
          "=r"((r)[8]),  "=r"((r)[9]),  "=r"((r)[10]), "=r"((r)[11]), \
          "=r"((r)[12]), "=r"((r)[13]), "=r"((r)[14]), "=r"((r)[15]), \
          "=r"((r)[16]), "=r"((r)[17]), "=r"((r)[18]), "=r"((r)[19]), \
          "=r"((r)[20]), "=r"((r)[21]), "=r"((r)[22]), "=r"((r)[23]), \
          "=r"((r)[24]), "=r"((r)[25]), "=r"((r)[26]), "=r"((r)[27]), \
          "=r"((r)[28]), "=r"((r)[29]), "=r"((r)[30]), "=r"((r)[31]) \
        : "r"(tmem_addr))

// cg2 MMA: 8 disable-lane regs
static __device__ __forceinline__ void mma_tf32_cg2(
    uint32_t d_tmem, uint64_t a_desc, uint64_t b_desc, uint32_t idesc, uint32_t en) {
    asm volatile(
        "{\n\t"
        ".reg .pred p;\n\t"
        "setp.ne.u32 p, %5, 0;\n\t"
        "tcgen05.mma.cta_group::2.kind::tf32 [%0], %1, %2, %3, "
        "{%4, %4, %4, %4, %4, %4, %4, %4}, p;\n\t"
        "}"
        :: "r"(d_tmem), "l"(a_desc), "l"(b_desc), "r"(idesc), "r"(0u), "r"(en)
        : "memory");
}

// ---------------- fused prepass: x-round + W-mask-round, one launch ----------------
#define PREP_XBLOCKS 8192     // 8192*1024 / (256*4)
#define PREP_WBLOCKS 3072     // 3072*1024 / (256*4)
__global__ void prep_fused_kernel(const float* __restrict__ x,
                                  const float* __restrict__ W,
                                  const float* __restrict__ wv) {
    const int bb = blockIdx.x;
    if (bb < PREP_XBLOCKS) {
        const size_t i = ((size_t)bb * blockDim.x + threadIdx.x) * 4;
        float4 v = *reinterpret_cast<const float4*>(x + i);
        v.x = cvt_tf32(v.x); v.y = cvt_tf32(v.y);
        v.z = cvt_tf32(v.z); v.w = cvt_tf32(v.w);
        *reinterpret_cast<float4*>(g_xr + i) = v;
    } else {
        const float s45  = wv[4] + wv[5];
        const float s23  = wv[2] + wv[3] + s45;
        const float sall = wv[0] + wv[1] + s23;
        const size_t i = ((size_t)(bb - PREP_XBLOCKS) * blockDim.x + threadIdx.x) * 4;
        const int o = (int)(i >> 10);
        const int k = (int)(i & 1023);
        const int ob = (o >= 1536) + (o >= 2304);
        float m;
        if (k >= 768)       m = s45;
        else if (k >= 512)  m = (ob <= 1) ? s23 : s45;
        else                m = (ob == 0) ? sall : (ob == 1 ? s23 : s45);
        float4 v = *reinterpret_cast<const float4*>(W + i);
        v.x = cvt_tf32(v.x * m); v.y = cvt_tf32(v.y * m);
        v.z = cvt_tf32(v.z * m); v.w = cvt_tf32(v.w * m);
        *reinterpret_cast<float4*>(g_wr + i) = v;
    }
}

// ---------------- persistent GEMM kernel ----------------
__global__ void __launch_bounds__(THREADS, 1) __cluster_dims__(CLUSTER, 1, 1)
gemm_tf32_kernel(const float* __restrict__ x, const float* __restrict__ wv,
                 const float* __restrict__ W, const float* __restrict__ bias,
                 float* __restrict__ out,
                 const __grid_constant__ CUtensorMap tmap_a,
                 const __grid_constant__ CUtensorMap tmap_b) {
    const int t = threadIdx.x;
    const int pair = blockIdx.x >> 1;

    const float s45  = wv[4] + wv[5];
    const float s23  = wv[2] + wv[3] + s45;
    const float sall = wv[0] + wv[1] + s23;

#if USE_TCGEN05
    const uint32_t rank = cluster_rank();
    extern __shared__ char smem[];
    const uint32_t sb = smem_u32(smem);
    const int wid = t >> 5;
    const int lid = t & 31;

    if (wid == 0) {
        if (elect_one()) {
#pragma unroll
            for (int s = 0; s < STAGES; ++s) {
                MBARRIER_INIT(sb + SM_FULL(s), 1);
                MBARRIER_INIT(sb + SM_EMPTY(s), 1);
            }
#pragma unroll
            for (int b2 = 0; b2 < 2; ++b2) {
                MBARRIER_INIT(sb + SM_EPI_FULL(b2), 1);
                MBARRIER_INIT(sb + SM_EPI_EMPTY(b2), 2);
            }
        }
        TCGEN05_ALLOC_CG2(sb + SM_TMEM, 512);
    }
    __syncthreads();
    uint32_t tmem;
    asm volatile("ld.shared.b32 %0, [%1];" : "=r"(tmem) : "r"(sb + SM_TMEM));
    CLUSTER_SYNC();   // barriers live in both CTAs before any cg2 TMA / commit

    if (wid == 0) {
        // ================= MMA issuer (leader CTA only) =================
        if (rank == 0 && elect_one()) {
            int fph[STAGES] = {0, 0, 0, 0, 0, 0};
            int eph2[2] = {0, 0};
            int kg = 0, lt = 0;
#pragma unroll 1
            for (int tile = pair; tile < NTILES; tile += PAIRS, ++lt) {
                const int buf = lt & 1;
                const uint32_t dmem = tmem + buf * 256;
                if (lt >= 2) {
                    MBARRIER_WAIT_PARITY(sb + SM_EPI_EMPTY(buf), eph2[buf]);
                    eph2[buf] ^= 1;
                }
#pragma unroll 1
                for (int it = 0; it < NKIT; ++it, ++kg) {
                    const int s = kg % STAGES;
                    MBARRIER_WAIT_PARITY(sb + SM_FULL(s), fph[s]); fph[s] ^= 1;
                    const uint64_t ad = MK_DESC(sb + SM_A(s));
                    const uint64_t bd = MK_DESC(sb + SM_B(s));
#pragma unroll
                    for (int ks = 0; ks < 4; ++ks)
                        mma_tf32_cg2(dmem, ad + ks * 2, bd + ks * 2, IDESC_TF32,
                                     (uint32_t)(it > 0 || ks > 0));
                    TCGEN05_COMMIT_MC_CG2(sb + SM_EMPTY(s), 0x3);
                }
                TCGEN05_COMMIT_MC_CG2(sb + SM_EPI_FULL(buf), 0x3);
            }
        }
    } else if (wid == 1) {
        // ================= TMA producer (both CTAs) =================
        if (elect_one()) {
            int eph[STAGES] = {0, 0, 0, 0, 0, 0};
            int kg = 0;
#pragma unroll 1
            for (int tile = pair; tile < NTILES; tile += PAIRS) {
                const int m0 = (tile / 12) * BM + (int)rank * 128;
                const int brow = (tile % 12) * BN + (int)rank * 128;
#pragma unroll 1
                for (int it = 0; it < NKIT; ++it, ++kg) {
                    const int s = kg % STAGES;
                    if (kg >= STAGES) {
                        MBARRIER_WAIT_PARITY(sb + SM_EMPTY(s), eph[s]); eph[s] ^= 1;
                    }
                    if (rank == 0) MBARRIER_EXPECT_TX(sb + SM_FULL(s), 65536);
                    TMA_2D_CG2(sb + SM_A(s), &tmap_a, it * BK, m0,   sb + SM_FULL(s));
                    TMA_2D_CG2(sb + SM_B(s), &tmap_b, it * BK, brow, sb + SM_FULL(s));
                }
            }
        }
    } else if (wid < 4) {
        // ================= zero-fill mirror tiles (warps 2-3) =================
        const int p2 = t - 64;   // 0..63
        const float4 z = make_float4(0.f, 0.f, 0.f, 0.f);
#pragma unroll 1
        for (int tile = pair; tile < NTILES; tile += PAIRS) {
            const int m0 = (tile / 12) * BM + (int)rank * 128;
            const int n0z = (tile % 12) * BN + 3072;
            float* zt = out + (size_t)m0 * 6144 + n0z;
#pragma unroll 4
            for (int j = 0; j < 128; ++j) {
                const int idx = p2 + j * 64;      // < 8192
                const int row = idx >> 6, c4 = idx & 63;
                *reinterpret_cast<float4*>(zt + (size_t)row * 6144 + c4 * 4) = z;
            }
        }
    } else {
        // ================= epilogue (warps 4-7, both CTAs) =================
        const int row = (wid - 4) * 32 + lid;
        int fphE[2] = {0, 0};
        int lt = 0;
#pragma unroll 1
        for (int tile = pair; tile < NTILES; tile += PAIRS, ++lt) {
            const int buf = lt & 1;
            const uint32_t dmem = tmem + buf * 256;
            const int n0 = (tile % 12) * BN;
            const int m0 = (tile / 12) * BM + (int)rank * 128;
            const int oband = (n0 >= 1536) + (n0 >= 2304);
            const float bscale = (oband == 0) ? sall : (oband == 1 ? s23 : s45);

            MBARRIER_WAIT_PARITY(sb + SM_EPI_FULL(buf), fphE[buf]); fphE[buf] ^= 1;
            TCGEN05_FENCE_AFTER();

            float* orow = out + (size_t)(m0 + row) * 6144 + n0;
#pragma unroll
            for (int cb = 0; cb < 256; cb += 32) {
                uint32_t dr[32];
                TCGEN05_LD_32X32B_X32(dr, dmem + cb);
                TCGEN05_WAIT_LD();
#pragma unroll
                for (int cc = 0; cc < 32; cc += 4) {
                    const int col = n0 + cb + cc;
                    float4 v;
                    v.x = __uint_as_float(dr[cc + 0]) + bias[col + 0] * bscale;
                    v.y = __uint_as_float(dr[cc + 1]) + bias[col + 1] * bscale;
                    v.z = __uint_as_float(dr[cc + 2]) + bias[col + 2] * bscale;
                    v.w = __uint_as_float(dr[cc + 3]) + bias[col + 3] * bscale;
                    *reinterpret_cast<float4*>(orow + cb + cc) = v;
                }
            }
            TCGEN05_FENCE_BEFORE();
            asm volatile("bar.sync 14, 128;" ::: "memory");   // warps 4-7
            if (wid == 4 && elect_one())
                MBARRIER_ARRIVE_LEADER(sb + SM_EPI_EMPTY(buf));
        }
    }

    __syncthreads();
    if (wid == 0) {
        TCGEN05_RELINQUISH_CG2();
        TCGEN05_DEALLOC_CG2(tmem, 512);
    }
    CLUSTER_SYNC();   // no CTA exits while peer cg2 ops may target its smem
#else
    // SIMT fallback for the family-generic PTX pass (never executed on GB300).
    const int rankf = blockIdx.x & 1;
    for (int tile = pair; tile < NTILES; tile += PAIRS) {
        const int n0 = (tile % 12) * BN;
        const int m0 = (tile / 12) * BM + rankf * 128;
        const int oband = (n0 >= 1536) + (n0 >= 2304);
        const float bscale = (oband == 0) ? sall : (oband == 1 ? s23 : s45);
        float mv0, mv1, mv2;
        if (oband == 0)      { mv0 = sall; mv1 = s23; mv2 = s45; }
        else if (oband == 1) { mv0 = s23;  mv1 = s23; mv2 = s45; }
        else                 { mv0 = s45;  mv1 = s45; mv2 = s45; }
        for (int e = t; e < 128 * BN; e += THREADS) {
            const int r = e / BN, cc = e % BN;
            const float* xr = x + (size_t)(m0 + r) * 1024;
            const float* wr = W + (size_t)(n0 + cc) * 1024;
            float acc = 0.f;
            for (int k = 0; k < 1024; ++k) {
                const float m = (k < 512) ? mv0 : (k < 768 ? mv1 : mv2);
                acc += xr[k] * wr[k] * m;
            }
            out[(size_t)(m0 + r) * 6144 + n0 + cc] = acc + bias[n0 + cc] * bscale;
            out[(size_t)(m0 + r) * 6144 + n0 + cc + 3072] = 0.f;
        }
    }
#endif
}

// ---------------- launcher ----------------
typedef CUresult (*PFN_tmap_encode)(
    CUtensorMap*, CUtensorMapDataType, cuuint32_t, void*,
    const cuuint64_t*, const cuuint64_t*, const cuuint32_t*, const cuuint32_t*,
    CUtensorMapInterleave, CUtensorMapSwizzle, CUtensorMapL2promotion,
    CUtensorMapFloatOOBfill);

static void make_tmap(CUtensorMap* tm, void* base, cuuint64_t rows) {
    PFN_tmap_encode enc = nullptr;
    cudaDriverEntryPointQueryResult st;
    cudaGetDriverEntryPointByVersion("cuTensorMapEncodeTiled", (void**)&enc,
                                     12000, cudaEnableDefault, &st);
    cuuint64_t dims[2]    = {1024, rows};
    cuuint64_t strides[1] = {1024 * sizeof(float)};
    cuuint32_t box[2]     = {BK, 128};
    cuuint32_t estr[2]    = {1, 1};
    enc(tm, CU_TENSOR_MAP_DATA_TYPE_FLOAT32, 2, base,
        dims, strides, box, estr,
        CU_TENSOR_MAP_INTERLEAVE_NONE, CU_TENSOR_MAP_SWIZZLE_128B,
        CU_TENSOR_MAP_L2_PROMOTION_L2_128B, CU_TENSOR_MAP_FLOAT_OOB_FILL_NONE);
}

extern "C" void kernel_launch(void* const* d_in, const int* in_sizes, int n_in,
                              void* d_out, int out_size) {
    const float *x = nullptr, *wv = nullptr, *W = nullptr, *b = nullptr;
    for (int i = 0; i < n_in; ++i) {
        switch (in_sizes[i]) {
            case 8388608: x  = (const float*)d_in[i]; break;
            case 6:       wv = (const float*)d_in[i]; break;
            case 6291456: W  = (const float*)d_in[i]; break;
            case 6144:    b  = (const float*)d_in[i]; break;
        }
    }
    if (!x)  x  = (const float*)d_in[0];
    if (!wv) wv = (const float*)d_in[1];
    if (!W)  W  = (const float*)d_in[2];
    if (!b)  b  = (const float*)d_in[3];
    float* out = (float*)d_out;

    void* xr_ptr = nullptr; void* wr_ptr = nullptr;
    cudaGetSymbolAddress(&xr_ptr, g_xr);
    cudaGetSymbolAddress(&wr_ptr, g_wr);
    CUtensorMap tmap_a, tmap_b;
    make_tmap(&tmap_a, xr_ptr, 8192);
    make_tmap(&tmap_b, wr_ptr, 3072);

    cudaFuncSetAttribute(gemm_tf32_kernel,
                         cudaFuncAttributeMaxDynamicSharedMemorySize, SM_TOTAL);

    prep_fused_kernel<<<PREP_XBLOCKS + PREP_WBLOCKS, 256>>>(x, W, wv);
    gemm_tf32_kernel<<<PAIRS * CLUSTER, THREADS, SM_TOTAL>>>(x, wv, W, b, out,
                                                             tmap_a, tmap_b);
}